// round 9
// baseline (speedup 1.0000x reference)
#include <cuda_runtime.h>
#include <cstdint>

#define NQ   22
#define DIM  (1u << NQ)     // 4194304 elements per component

// ---- tiny diagonal split tables (device globals, no allocation) ----
// diag[b] = dLo[b&2047] + dHi[b>>11] + sum_{h set in (b>>11)} R[h][b&2047]
__device__ float g_dLo[2048];
__device__ float g_dHi[2048];
__device__ float g_R[11][2048];

__device__ __forceinline__ void add4(float4& a, const float4 b) {
    a.x += b.x; a.y += b.y; a.z += b.z; a.w += b.w;
}

__device__ __forceinline__ uint32_t smem_u32(const void* p) {
    uint32_t a;
    asm("{ .reg .u64 t; cvta.to.shared.u64 t, %1; cvt.u32.u64 %0, t; }"
        : "=r"(a) : "l"(p));
    return a;
}
__device__ __forceinline__ void cpasync16(uint32_t s, const void* g) {
    asm volatile("cp.async.cg.shared.global [%0], [%1], 16;" :: "r"(s), "l"(g));
}
#define CP_COMMIT() asm volatile("cp.async.commit_group;")
#define CP_WAIT0()  asm volatile("cp.async.wait_group 0;")

// ---------------------------------------------------------------------------
// Diag tables, computed by K1 CTAs (x<2, y==0), 1024 entries each.
// Read only by K2 (safe across the kernel boundary).
// ---------------------------------------------------------------------------
__device__ void compute_tables(const float* __restrict__ U,
                               const float* __restrict__ detune,
                               float* sU /* >= 485 floats */)
{
    for (int i = threadIdx.x; i < NQ * NQ; i += 1024) sU[i] = U[i];
    if (threadIdx.x == 0) sU[NQ * NQ] = detune[0];
    __syncthreads();
    const float det = sU[NQ * NQ];
    const int t = blockIdx.x * 1024 + threadIdx.x;   // 0..2047

    float dlo = 0.f;
#pragma unroll
    for (int p = 0; p < 11; p++) {
        if ((t >> p) & 1) {
            dlo -= det;
#pragma unroll
            for (int q = 0; q < p; q++)
                if ((t >> q) & 1) dlo += sU[(21 - p) * NQ + (21 - q)];
        }
    }
    g_dLo[t] = dlo;

    float dhi = 0.f;
#pragma unroll
    for (int h = 0; h < 11; h++) {
        if ((t >> h) & 1) {
            dhi -= det;
#pragma unroll
            for (int h2 = 0; h2 < h; h2++)
                if ((t >> h2) & 1) dhi += sU[(10 - h) * NQ + (10 - h2)];
        }
    }
    g_dHi[t] = dhi;

#pragma unroll
    for (int h = 0; h < 11; h++) {
        float r = 0.f;
#pragma unroll
        for (int q = 0; q < 11; q++)
            if ((t >> q) & 1) r += sU[(10 - h) * NQ + (21 - q)];
        g_R[h][t] = r;
    }
}

// ---------------------------------------------------------------------------
// K1: low bits 0..13 (14 X-neighbors), writes out = c*acc. No diag.
//   Component-split (blockIdx.y). One-comp tile = 16384 consecutive elems
//   = 64KB = 4096 f4. 1024 threads, 4 f4/thread: G = tid + k*1024.
//   bits 0..1  : in-float4 swaps
//   bits 2..11 : 10 smem XOR dirs (G bits 0..9 = tid)
//   bits 12..13: register dirs k^1, k^2
//   CTAs (x<2, y==0) also compute the diag tables while their fill flies.
// ---------------------------------------------------------------------------
__global__ void __launch_bounds__(1024, 2)
k1_low_kernel(const float* __restrict__ sr, const float* __restrict__ si,
              const float* __restrict__ rabi, float* __restrict__ out,
              const float* __restrict__ U, const float* __restrict__ detune)
{
    extern __shared__ float4 sv[];     // 4096 f4 = 64KB (one component)
    __shared__ float sU[NQ * NQ + 1];
    const uint32_t sb = smem_u32(sv);
    const int tid = threadIdx.x;
    const int comp = blockIdx.y;
    const float* src = comp ? si : sr;
    const float4* g4 = (const float4*)src;
    float4* o4 = (float4*)(out + (unsigned)comp * DIM);
    const unsigned gbase = (unsigned)blockIdx.x << 12;   // f4-group base

#pragma unroll
    for (int j = 0; j < 4; j++) {
        const int idx = tid + j * 1024;
        cpasync16(sb + idx * 16, g4 + gbase + idx);
    }
    CP_COMMIT();
    const float c = 0.5f * __ldg(rabi);

    if (blockIdx.x < 2 && comp == 0) compute_tables(U, detune, sU);

    CP_WAIT0();
    __syncthreads();

    float4 v[4];
#pragma unroll
    for (int k = 0; k < 4; k++) v[k] = sv[tid + k * 1024];

#pragma unroll
    for (int k = 0; k < 4; k++) {
        const int G = tid + k * 1024;
        const float4 s = v[k];

        // bits 0..1 (in-float4) + register dirs (bits 12..13)
        float4 a = make_float4(s.y + s.z, s.x + s.w, s.w + s.x, s.z + s.y);
        add4(a, v[k ^ 1]);
        add4(a, v[k ^ 2]);

        // 10 smem dirs (bits 2..11), two waves of 5 to bound live temps
        float4 t0 = sv[G ^ 1],  t1 = sv[G ^ 2],  t2 = sv[G ^ 4];
        float4 t3 = sv[G ^ 8],  t4 = sv[G ^ 16];
        add4(t0, t1); add4(t2, t3); add4(t4, a);
        add4(t0, t2); add4(t4, t0);

        float4 u0 = sv[G ^ 32],  u1 = sv[G ^ 64],  u2 = sv[G ^ 128];
        float4 u3 = sv[G ^ 256], u4 = sv[G ^ 512];
        add4(u0, u1); add4(u2, u3); add4(u4, t4);
        add4(u0, u2); add4(u4, u0);

        o4[gbase + G] = make_float4(c * u4.x, c * u4.y, c * u4.z, c * u4.w);
    }
}

// ---------------------------------------------------------------------------
// K2: high bits 14..21 (8 X-neighbors) + diagonal, RMW into out.
//   Component-split (blockIdx.y). mid = elem bits 5..13 (grid.x = 512).
//   Tile = 256 combos (bits 14..21) x 32-elem rows (bits 0..4, 128B!) =
//   8192 elems = 32KB = 2048 f4. 1024 threads, 2 f4/thread:
//   idx = tid + k*1024 -> rf8 = idx&7 (f4 in row), combo = idx>>3
//   (bits 0..6 = tid>>3, bit 7 = k).
//   bits 14..20: 7 smem XOR dirs; bit 21: register dir k^1.
//   diag: lo fixed per thread; hi = midhi | cb7<<3 | k<<10.
//   out += c*acc + diag .* psi   (RMW values prefetched early, plain loads)
// ---------------------------------------------------------------------------
__global__ void __launch_bounds__(1024, 2)
k2_high_kernel(const float* __restrict__ sr, const float* __restrict__ si,
               const float* __restrict__ rabi, float* __restrict__ out)
{
    extern __shared__ float4 sv[];     // 2048 f4 = 32KB (one component)
    const uint32_t sb = smem_u32(sv);
    const int tid = threadIdx.x;
    const int comp = blockIdx.y;
    const unsigned mid = blockIdx.x;               // elem bits 5..13
    const float* src = comp ? si : sr;
    const float4* g4 = (const float4*)src;
    float4* o4 = (float4*)(out + (unsigned)comp * DIM);

    const int rf8 = tid & 7;                       // f4 within 32-elem row
    const int cb7 = tid >> 3;                      // combo bits 0..6

    // global f4 index for tile f4 idx: combo<<12 | mid<<3 | rf8
#pragma unroll
    for (int j = 0; j < 2; j++) {
        const int idx = tid + j * 1024;
        const unsigned gG = ((unsigned)(idx >> 3) << 12) + (mid << 3) + (idx & 7);
        cpasync16(sb + idx * 16, g4 + gG);
    }
    CP_COMMIT();
    const float c = 0.5f * __ldg(rabi);

    // ---- diag staging (L1 loads; overlaps the cp.async fill) ----
    const int lo4 = (int)((mid & 63u) << 5) | (rf8 << 2);  // elem bits 0..10, f4 base
    const int midhi = (int)(mid >> 6);                      // hi bits 0..2
    float4 base4 = __ldg((const float4*)&g_dLo[lo4]);
    if (midhi & 1) add4(base4, __ldg((const float4*)&g_R[0][lo4]));
    if (midhi & 2) add4(base4, __ldg((const float4*)&g_R[1][lo4]));
    if (midhi & 4) add4(base4, __ldg((const float4*)&g_R[2][lo4]));
#pragma unroll
    for (int t = 0; t < 7; t++)
        if ((cb7 >> t) & 1) add4(base4, __ldg((const float4*)&g_R[t + 3][lo4]));
    const float4 r10 = __ldg((const float4*)&g_R[10][lo4]);
    const float dh0 = __ldg(&g_dHi[(unsigned)midhi | ((unsigned)cb7 << 3)]);
    const float dh1 = __ldg(&g_dHi[(unsigned)midhi | ((unsigned)cb7 << 3) | 1024u]);

    CP_WAIT0();
    __syncthreads();

    // prefetch RMW targets so their L2/DRAM latency overlaps the LDS work
    float4 o0, o1;
    {
        const unsigned gG0 = ((unsigned)(tid >> 3) << 12) + (mid << 3) + rf8;
        const unsigned gG1 = ((unsigned)((tid + 1024) >> 3) << 12) + (mid << 3) + rf8;
        o0 = o4[gG0];
        o1 = o4[gG1];
    }

    float4 v[2];
    v[0] = sv[tid];
    v[1] = sv[tid + 1024];

#pragma unroll
    for (int k = 0; k < 2; k++) {
        const int idx = tid + k * 1024;

        // 7 smem dirs (elem bits 14..20) + 1 reg dir (bit 21)
        float4 t0 = sv[idx ^ 8],   t1 = sv[idx ^ 16],  t2 = sv[idx ^ 32];
        float4 t3 = sv[idx ^ 64],  t4 = sv[idx ^ 128], t5 = sv[idx ^ 256];
        float4 t6 = sv[idx ^ 512];
        add4(t0, t1); add4(t2, t3); add4(t4, t5);
        add4(t6, v[k ^ 1]);
        add4(t0, t2); add4(t4, t6);
        add4(t0, t4);

        // diagonal weight
        float4 W = base4;
        if (k) add4(W, r10);
        const float dh = k ? dh1 : dh0;
        W.x += dh; W.y += dh; W.z += dh; W.w += dh;

        float4 oo = k ? o1 : o0;
        oo.x = fmaf(c, t0.x, fmaf(W.x, v[k].x, oo.x));
        oo.y = fmaf(c, t0.y, fmaf(W.y, v[k].y, oo.y));
        oo.z = fmaf(c, t0.z, fmaf(W.z, v[k].z, oo.z));
        oo.w = fmaf(c, t0.w, fmaf(W.w, v[k].w, oo.w));
        const unsigned gG = ((unsigned)(idx >> 3) << 12) + (mid << 3) + (idx & 7);
        o4[gG] = oo;
    }
}

// ---------------------------------------------------------------------------
// Launch: K1 (bits 0..13, writes out; also builds tables)
//      -> K2 (bits 14..21 + diag, RMW out). Component-split grids.
// ---------------------------------------------------------------------------
extern "C" void kernel_launch(void* const* d_in, const int* in_sizes, int n_in,
                              void* d_out, int out_size)
{
    const float* sr     = (const float*)d_in[0];
    const float* si     = (const float*)d_in[1];
    const float* rabi   = (const float*)d_in[2];
    const float* detune = (const float*)d_in[3];
    const float* U      = (const float*)d_in[4];
    float* out = (float*)d_out;

    cudaFuncSetAttribute(k1_low_kernel,
                         cudaFuncAttributeMaxDynamicSharedMemorySize, 65536);
    cudaFuncSetAttribute(k2_high_kernel,
                         cudaFuncAttributeMaxDynamicSharedMemorySize, 32768);

    k1_low_kernel<<<dim3(256, 2), 1024, 65536>>>(sr, si, rabi, out, U, detune);
    k2_high_kernel<<<dim3(512, 2), 1024, 32768>>>(sr, si, rabi, out);
}

// round 10
// speedup vs baseline: 1.4936x; 1.4936x over previous
#include <cuda_runtime.h>
#include <cstdint>

#define NQ   22
#define DIM  (1u << NQ)     // 4194304 elements per component

// ---- tiny diagonal split tables (device globals, no allocation) ----
// diag[b] = dLo[b&2047] + dHi[b>>11] + sum_{h set in (b>>11)} R[h][b&2047]
__device__ float g_dLo[2048];
__device__ float g_dHi[2048];
__device__ float g_R[11][2048];

__device__ __forceinline__ void add4(float4& a, const float4 b) {
    a.x += b.x; a.y += b.y; a.z += b.z; a.w += b.w;
}

__device__ __forceinline__ uint32_t smem_u32(const void* p) {
    uint32_t a;
    asm("{ .reg .u64 t; cvta.to.shared.u64 t, %1; cvt.u32.u64 %0, t; }"
        : "=r"(a) : "l"(p));
    return a;
}
__device__ __forceinline__ void cpasync16(uint32_t s, const void* g) {
    asm volatile("cp.async.cg.shared.global [%0], [%1], 16;" :: "r"(s), "l"(g));
}
#define CP_COMMIT() asm volatile("cp.async.commit_group;")
#define CP_WAIT0()  asm volatile("cp.async.wait_group 0;")

// ---------------------------------------------------------------------------
// Tables kernel (runs before K1; K1 and K2 both read the results).
// ---------------------------------------------------------------------------
__global__ void __launch_bounds__(256)
tables_kernel(const float* __restrict__ U, const float* __restrict__ detune)
{
    __shared__ float sU[NQ * NQ + 1];
    for (int i = threadIdx.x; i < NQ * NQ; i += 256) sU[i] = U[i];
    if (threadIdx.x == 0) sU[NQ * NQ] = detune[0];
    __syncthreads();
    const float det = sU[NQ * NQ];
    const int t = blockIdx.x * 256 + threadIdx.x;   // 0..2047

    float dlo = 0.f;
#pragma unroll
    for (int p = 0; p < 11; p++) {
        if ((t >> p) & 1) {
            dlo -= det;
#pragma unroll
            for (int q = 0; q < p; q++)
                if ((t >> q) & 1) dlo += sU[(21 - p) * NQ + (21 - q)];
        }
    }
    g_dLo[t] = dlo;

    float dhi = 0.f;
#pragma unroll
    for (int h = 0; h < 11; h++) {
        if ((t >> h) & 1) {
            dhi -= det;
#pragma unroll
            for (int h2 = 0; h2 < h; h2++)
                if ((t >> h2) & 1) dhi += sU[(10 - h) * NQ + (10 - h2)];
        }
    }
    g_dHi[t] = dhi;

#pragma unroll
    for (int h = 0; h < 11; h++) {
        float r = 0.f;
#pragma unroll
        for (int q = 0; q < 11; q++)
            if ((t >> q) & 1) r += sU[(10 - h) * NQ + (21 - q)];
        g_R[h][t] = r;
    }
}

// ---------------------------------------------------------------------------
// K1: low bits 0..13 (14 X-neighbors) + FULL diagonal; writes
//   out = c*acc_low + diag .* psi.
//   Component-split (blockIdx.y). Tile = 16384 consecutive elems = 64KB =
//   4096 f4. 512 threads, 8 f4/thread: G = tid + k*512 (k = elem bits 11..13).
//   bits 0..1  : in-float4 swaps
//   bits 2..10 : 9 smem XOR dirs (G bits 0..8 = tid)
//   bits 11..13: register dirs k^1, k^2, k^4
//   diag: per-thread lo f4 is FIXED across k (lo4 = tid*4) ->
//     D0 = dLo[lo4] + sum over CTA-fixed hi bits (R rows 3..10, warp-uniform
//     predicates); R0/R1 in regs; R2 folded into D0 at k==4;
//     dHi[(bx<<3)|k] uniform scalar per k.
// ---------------------------------------------------------------------------
__global__ void __launch_bounds__(512, 2)
k1_low_kernel(const float* __restrict__ sr, const float* __restrict__ si,
              const float* __restrict__ rabi, float* __restrict__ out)
{
    extern __shared__ float4 sv[];     // 4096 f4 = 64KB (one component)
    const uint32_t sb = smem_u32(sv);
    const int tid = threadIdx.x;
    const int bx = blockIdx.x;                       // elem bits 14..21
    const int comp = blockIdx.y;
    const float4* g4 = (const float4*)(comp ? si : sr);
    float4* o4 = (float4*)(out + (unsigned)comp * DIM);
    const unsigned gbase = (unsigned)bx << 12;       // f4-group base

#pragma unroll
    for (int j = 0; j < 8; j++) {
        const int idx = tid + j * 512;
        cpasync16(sb + idx * 16, g4 + gbase + idx);
    }
    CP_COMMIT();
    const float c = 0.5f * __ldg(rabi);

    // ---- diag staging: all L1/L2 loads overlap the cp.async fill ----
    const int lo4 = tid << 2;                        // elem bits 0..10, f4 base
    float4 D0 = __ldg((const float4*)&g_dLo[lo4]);
#pragma unroll
    for (int t = 0; t < 8; t++)
        if ((bx >> t) & 1) add4(D0, __ldg((const float4*)&g_R[t + 3][lo4]));
    const float4 R0 = __ldg((const float4*)&g_R[0][lo4]);
    const float4 R1 = __ldg((const float4*)&g_R[1][lo4]);

    CP_WAIT0();
    __syncthreads();

    float4 v[8];
#pragma unroll
    for (int k = 0; k < 8; k++) v[k] = sv[tid + k * 512];

#pragma unroll
    for (int k = 0; k < 8; k++) {
        if (k == 4) add4(D0, __ldg((const float4*)&g_R[2][lo4]));  // fold R2
        const int G = tid + k * 512;
        const float4 s = v[k];

        // bits 0..1 (in-float4) + register dirs (bits 11..13)
        float4 a = make_float4(s.y + s.z, s.x + s.w, s.w + s.x, s.z + s.y);
        add4(a, v[k ^ 1]);
        add4(a, v[k ^ 2]);
        add4(a, v[k ^ 4]);

        // 9 smem dirs (bits 2..10), two waves to bound live temps
        float4 t0 = sv[G ^ 1],  t1 = sv[G ^ 2],  t2 = sv[G ^ 4];
        float4 t3 = sv[G ^ 8];
        add4(t0, t1); add4(t2, t3);
        add4(a, t0);  add4(a, t2);

        float4 u0 = sv[G ^ 16],  u1 = sv[G ^ 32],  u2 = sv[G ^ 64];
        float4 u3 = sv[G ^ 128], u4 = sv[G ^ 256];
        add4(u0, u1); add4(u2, u3);
        add4(u0, u2); add4(u4, a);
        add4(u4, u0);

        // diagonal weight (k compile-time -> predicates are free)
        float4 W = D0;
        if (k & 1) add4(W, R0);
        if (k & 2) add4(W, R1);
        const float dh = __ldg(&g_dHi[((unsigned)bx << 3) | k]);
        W.x += dh; W.y += dh; W.z += dh; W.w += dh;

        float4 o;
        o.x = fmaf(c, u4.x, W.x * s.x);
        o.y = fmaf(c, u4.y, W.y * s.y);
        o.z = fmaf(c, u4.z, W.z * s.z);
        o.w = fmaf(c, u4.w, W.w * s.w);
        o4[gbase + G] = o;
    }
}

// ---------------------------------------------------------------------------
// K2: high bits 14..21 (8 X-neighbors), diag-free RMW: out += c*acc.
//   Component-split (blockIdx.y). blockIdx.x = b21<<9 | mid, mid = elem bits
//   5..13 (512), b21 = elem bit 21 (tile-fixed).
//   Tile = 128 combos (elem bits 14..20) x 32-elem rows (128B) = 16KB =
//   1024 f4. 512 threads, 2 f4/thread: idx = tid + k*512, rf8 = idx&7,
//   c7 = idx>>3 (bit 6 of c7 = k = elem bit 20).
//   bits 14..19: 6 smem XOR dirs; bit 20: reg dir k^1;
//   bit 21: coalesced GLOBAL dir (gG ^ 1<<19).
//   o and bit-21 neighbors prefetched before the fill wait (full MLP).
// ---------------------------------------------------------------------------
__global__ void __launch_bounds__(512, 3)
k2_high_kernel(const float* __restrict__ sr, const float* __restrict__ si,
               const float* __restrict__ rabi, float* __restrict__ out)
{
    extern __shared__ float4 sv[];     // 1024 f4 = 16KB (one component)
    const uint32_t sb = smem_u32(sv);
    const int tid = threadIdx.x;
    const int comp = blockIdx.y;
    const unsigned mid = blockIdx.x & 511u;          // elem bits 5..13
    const unsigned b21 = blockIdx.x >> 9;            // elem bit 21
    const float4* g4 = (const float4*)(comp ? si : sr);
    float4* o4 = (float4*)(out + (unsigned)comp * DIM);

    // global f4 index for tile f4 idx
    const unsigned gG0 = (b21 << 19) + ((unsigned)(tid >> 3) << 12) + (mid << 3) + (tid & 7);
    const unsigned gG1 = gG0 + (64u << 12);          // idx + 512 -> c7 += 64

#pragma unroll
    for (int j = 0; j < 2; j++) {
        const int idx = tid + j * 512;
        const unsigned gG = j ? gG1 : gG0;
        cpasync16(sb + idx * 16, g4 + gG);
    }
    CP_COMMIT();
    const float c = 0.5f * __ldg(rabi);

    // prefetch RMW targets + bit-21 global neighbors: independent of smem,
    // so their latency hides entirely behind the fill.
    float4 o0 = o4[gG0];
    float4 o1 = o4[gG1];
    float4 n0 = __ldg(&g4[gG0 ^ (1u << 19)]);
    float4 n1 = __ldg(&g4[gG1 ^ (1u << 19)]);

    CP_WAIT0();
    __syncthreads();

    float4 v0 = sv[tid];
    float4 v1 = sv[tid + 512];

    // ---- k = 0 ----
    {
        const int idx = tid;
        float4 t0 = sv[idx ^ 8],   t1 = sv[idx ^ 16],  t2 = sv[idx ^ 32];
        float4 t3 = sv[idx ^ 64],  t4 = sv[idx ^ 128], t5 = sv[idx ^ 256];
        add4(t0, t1); add4(t2, t3); add4(t4, t5);
        add4(t0, v1);                   // reg dir (bit 20)
        add4(t2, n0);                   // global dir (bit 21)
        add4(t0, t2); add4(t0, t4);
        o0.x = fmaf(c, t0.x, o0.x);
        o0.y = fmaf(c, t0.y, o0.y);
        o0.z = fmaf(c, t0.z, o0.z);
        o0.w = fmaf(c, t0.w, o0.w);
        o4[gG0] = o0;
    }
    // ---- k = 1 ----
    {
        const int idx = tid + 512;
        float4 t0 = sv[idx ^ 8],   t1 = sv[idx ^ 16],  t2 = sv[idx ^ 32];
        float4 t3 = sv[idx ^ 64],  t4 = sv[idx ^ 128], t5 = sv[idx ^ 256];
        add4(t0, t1); add4(t2, t3); add4(t4, t5);
        add4(t0, v0);                   // reg dir (bit 20)
        add4(t2, n1);                   // global dir (bit 21)
        add4(t0, t2); add4(t0, t4);
        o1.x = fmaf(c, t0.x, o1.x);
        o1.y = fmaf(c, t0.y, o1.y);
        o1.z = fmaf(c, t0.z, o1.z);
        o1.w = fmaf(c, t0.w, o1.w);
        o4[gG1] = o1;
    }
}

// ---------------------------------------------------------------------------
// Launch: tables -> K1 (bits 0..13 + diag, writes out)
//                -> K2 (bits 14..21, RMW out).
// ---------------------------------------------------------------------------
extern "C" void kernel_launch(void* const* d_in, const int* in_sizes, int n_in,
                              void* d_out, int out_size)
{
    const float* sr     = (const float*)d_in[0];
    const float* si     = (const float*)d_in[1];
    const float* rabi   = (const float*)d_in[2];
    const float* detune = (const float*)d_in[3];
    const float* U      = (const float*)d_in[4];
    float* out = (float*)d_out;

    cudaFuncSetAttribute(k1_low_kernel,
                         cudaFuncAttributeMaxDynamicSharedMemorySize, 65536);
    cudaFuncSetAttribute(k2_high_kernel,
                         cudaFuncAttributeMaxDynamicSharedMemorySize, 16384);

    tables_kernel<<<8, 256>>>(U, detune);
    k1_low_kernel<<<dim3(256, 2), 512, 65536>>>(sr, si, rabi, out);
    k2_high_kernel<<<dim3(1024, 2), 512, 16384>>>(sr, si, rabi, out);
}